// round 10
// baseline (speedup 1.0000x reference)
#include <cuda_runtime.h>

// BaseEBM: 1M samples x 20 GD steps on y through fixed 2->32->32->32->1
// ReLU MLP. R10: THREE samples/thread (weight-LDS per sample x2/3; R9
// showed fma=66%/L1=67% co-binding) + packed fma.rn.f32x2. Real row loops
// (#pragma unroll 1) keep ptxas live ranges bounded (the R5/R7/R8 spill
// killer). Three NAMED u64 accumulator banks (A/C/E = samples 0/1/2).
// Handoffs via shared scratch: u64 bank (samples 0,1) + f32 bank (sample 2).
// __launch_bounds__(64,5) -> ~200-reg budget for a ~150-reg design.

#define W 32
#define INNER_STEPS 20
#define INNER_LR 0.1f
#define TPB 64

using u64 = unsigned long long;

__device__ __forceinline__ u64 fma2(u64 a, u64 b, u64 c) {
    u64 d;
    asm("fma.rn.f32x2 %0, %1, %2, %3;" : "=l"(d) : "l"(a), "l"(b), "l"(c));
    return d;
}
__device__ __forceinline__ u64 dup2(float x) {
    u64 d;
    asm("mov.b64 %0, {%1, %1};" : "=l"(d) : "f"(x));
    return d;
}
__device__ __forceinline__ u64 pack2(float lo, float hi) {
    u64 d;
    asm("mov.b64 %0, {%1, %2};" : "=l"(d) : "f"(lo), "f"(hi));
    return d;
}
__device__ __forceinline__ void unpk(u64 v, float& lo, float& hi) {
    asm("mov.b64 {%0, %1}, %2;" : "=f"(lo), "=f"(hi) : "l"(v));
}

#define APPLY16(M) M(0) M(1) M(2) M(3) M(4) M(5) M(6) M(7) \
                   M(8) M(9) M(10) M(11) M(12) M(13) M(14) M(15)

// A/C/E banks += D0/D1/D2 * row[pair]. 8x LDS.128, 48x FFMA2.
#define ROWFMA3(ROW, D0, D1, D2) do {                                      \
    const ulonglong2* _r = reinterpret_cast<const ulonglong2*>(ROW);       \
    {                                                                      \
        ulonglong2 _wa = _r[0], _wb = _r[1], _wc = _r[2], _wd = _r[3];     \
        A0 = fma2(_wa.x, D0, A0); C0 = fma2(_wa.x, D1, C0); E0 = fma2(_wa.x, D2, E0); \
        A1 = fma2(_wa.y, D0, A1); C1 = fma2(_wa.y, D1, C1); E1 = fma2(_wa.y, D2, E1); \
        A2 = fma2(_wb.x, D0, A2); C2 = fma2(_wb.x, D1, C2); E2 = fma2(_wb.x, D2, E2); \
        A3 = fma2(_wb.y, D0, A3); C3 = fma2(_wb.y, D1, C3); E3 = fma2(_wb.y, D2, E3); \
        A4 = fma2(_wc.x, D0, A4); C4 = fma2(_wc.x, D1, C4); E4 = fma2(_wc.x, D2, E4); \
        A5 = fma2(_wc.y, D0, A5); C5 = fma2(_wc.y, D1, C5); E5 = fma2(_wc.y, D2, E5); \
        A6 = fma2(_wd.x, D0, A6); C6 = fma2(_wd.x, D1, C6); E6 = fma2(_wd.x, D2, E6); \
        A7 = fma2(_wd.y, D0, A7); C7 = fma2(_wd.y, D1, C7); E7 = fma2(_wd.y, D2, E7); \
    }                                                                      \
    {                                                                      \
        ulonglong2 _wa = _r[4], _wb = _r[5], _wc = _r[6], _wd = _r[7];     \
        A8  = fma2(_wa.x, D0, A8 ); C8  = fma2(_wa.x, D1, C8 ); E8  = fma2(_wa.x, D2, E8 ); \
        A9  = fma2(_wa.y, D0, A9 ); C9  = fma2(_wa.y, D1, C9 ); E9  = fma2(_wa.y, D2, E9 ); \
        A10 = fma2(_wb.x, D0, A10); C10 = fma2(_wb.x, D1, C10); E10 = fma2(_wb.x, D2, E10); \
        A11 = fma2(_wb.y, D0, A11); C11 = fma2(_wb.y, D1, C11); E11 = fma2(_wb.y, D2, E11); \
        A12 = fma2(_wc.x, D0, A12); C12 = fma2(_wc.x, D1, C12); E12 = fma2(_wc.x, D2, E12); \
        A13 = fma2(_wc.y, D0, A13); C13 = fma2(_wc.y, D1, C13); E13 = fma2(_wc.y, D2, E13); \
        A14 = fma2(_wd.x, D0, A14); C14 = fma2(_wd.x, D1, C14); E14 = fma2(_wd.x, D2, E14); \
        A15 = fma2(_wd.y, D0, A15); C15 = fma2(_wd.y, D1, C15); E15 = fma2(_wd.y, D2, E15); \
    }                                                                      \
} while (0)

__global__ __launch_bounds__(TPB, 5) void BaseEBM_kernel(
    const float* __restrict__ gX,
    const float* __restrict__ gW0,   // [32,2]
    const float* __restrict__ gB0,   // [32]
    const float* __restrict__ gW1,   // [32,32]
    const float* __restrict__ gB1,   // [32]
    const float* __restrict__ gW2,   // [32,32]
    const float* __restrict__ gB2,   // [32]
    const float* __restrict__ gW3,   // [32]
    const float* __restrict__ gYM,   // [1]
    float* __restrict__ gOUT,
    int n) {
    __shared__ alignas(16) float s_fw1[W * W];   // fw1[i*32+j] = W1[j][i]
    __shared__ alignas(16) float s_fw2[W * W];   // fw2[i*32+j] = W2[j][i]
    __shared__ alignas(16) float s_bw2[W * W];   // bw2[i*32+j] = W2[i][j]
    __shared__ alignas(16) float s_bw1[W * W];   // bw1[i*32+j] = W1[i][j]
    __shared__ alignas(16) float s_w0x[W];
    __shared__ alignas(16) float s_w0y[W];
    __shared__ alignas(16) float s_b0[W];
    __shared__ alignas(16) float s_b1[W];
    __shared__ alignas(16) float s_b2[W];
    __shared__ alignas(16) float s_w3[W];
    __shared__ u64   scrAB[W * TPB];   // samples 0,1 packed
    __shared__ float scrC[W * TPB];    // sample 2

    const int tid = threadIdx.x;
#pragma unroll
    for (int k = 0; k < (W * W) / TPB; k++) {
        int e = k * TPB + tid;
        int i = e >> 5, j = e & 31;
        s_fw1[e] = gW1[j * W + i];
        s_fw2[e] = gW2[j * W + i];
        s_bw2[e] = gW2[e];
        s_bw1[e] = gW1[e];
    }
    if (tid < W) {
        s_w0x[tid] = gW0[2 * tid + 0];
        s_w0y[tid] = gW0[2 * tid + 1];
        s_b0[tid]  = gB0[tid];
        s_b1[tid]  = gB1[tid];
        s_b2[tid]  = gB2[tid];
        s_w3[tid]  = gW3[tid];
    }
    __syncthreads();

    const int s0 = blockIdx.x * (3 * TPB) + tid;
    const int s1 = s0 + TPB;
    const int s2 = s0 + 2 * TPB;
    if (s0 >= n) return;

    const float x0 = gX[s0];
    const float x1 = (s1 < n) ? gX[s1] : 0.0f;
    const float x2 = (s2 < n) ? gX[s2] : 0.0f;
    float y0 = gYM[0];
    float y1 = y0, y2 = y0;

    const u64* b1p = reinterpret_cast<const u64*>(s_b1);
    const u64* b2p = reinterpret_cast<const u64*>(s_b2);
    u64*   pAB = scrAB + tid;
    float* pC  = scrC + tid;

    u64 A0, A1, A2, A3, A4, A5, A6, A7;
    u64 A8, A9, A10, A11, A12, A13, A14, A15;
    u64 C0, C1, C2, C3, C4, C5, C6, C7;
    u64 C8, C9, C10, C11, C12, C13, C14, C15;
    u64 E0, E1, E2, E3, E4, E5, E6, E7;
    u64 E8, E9, E10, E11, E12, E13, E14, E15;

#pragma unroll 1
    for (int s = 0; s < INNER_STEPS; s++) {
        unsigned m0a = 0u, m0b = 0u, m0c = 0u;
        unsigned m1a = 0u, m1b = 0u, m1c = 0u;
        unsigned m2a = 0u, m2b = 0u, m2c = 0u;

        // ---- matvec 1: acc = b1 + fw1^T relu(pre0)
#define INIT_B1(p) { u64 _b = b1p[p]; A##p = _b; C##p = _b; E##p = _b; }
        APPLY16(INIT_B1)
#undef INIT_B1
#pragma unroll 1
        for (int i = 0; i < W; i++) {
            float wx = s_w0x[i], wy = s_w0y[i], b = s_b0[i];
            float pa = fmaf(y0, wy, fmaf(x0, wx, b));
            float pb = fmaf(y1, wy, fmaf(x1, wx, b));
            float pc = fmaf(y2, wy, fmaf(x2, wx, b));
            m0a |= (pa > 0.0f) ? (1u << i) : 0u;
            m0b |= (pb > 0.0f) ? (1u << i) : 0u;
            m0c |= (pc > 0.0f) ? (1u << i) : 0u;
            u64 d0 = dup2(fmaxf(pa, 0.0f));
            u64 d1 = dup2(fmaxf(pb, 0.0f));
            u64 d2 = dup2(fmaxf(pc, 0.0f));
            ROWFMA3(s_fw1 + i * 32, d0, d1, d2);
        }

        // ---- acc = pre1. h1 = relu -> scratch; m1 recorded.
#define ST_H1(p) {                                                         \
        float _al, _ah, _cl, _ch, _el, _eh;                                \
        unpk(A##p, _al, _ah); unpk(C##p, _cl, _ch); unpk(E##p, _el, _eh);  \
        m1a |= (_al > 0.0f) ? (1u << (2 * p))     : 0u;                    \
        m1a |= (_ah > 0.0f) ? (1u << (2 * p + 1)) : 0u;                    \
        m1b |= (_cl > 0.0f) ? (1u << (2 * p))     : 0u;                    \
        m1b |= (_ch > 0.0f) ? (1u << (2 * p + 1)) : 0u;                    \
        m1c |= (_el > 0.0f) ? (1u << (2 * p))     : 0u;                    \
        m1c |= (_eh > 0.0f) ? (1u << (2 * p + 1)) : 0u;                    \
        pAB[(2 * p) * TPB]     = pack2(fmaxf(_al, 0.0f), fmaxf(_cl, 0.0f)); \
        pAB[(2 * p + 1) * TPB] = pack2(fmaxf(_ah, 0.0f), fmaxf(_ch, 0.0f)); \
        pC[(2 * p) * TPB]      = fmaxf(_el, 0.0f);                         \
        pC[(2 * p + 1) * TPB]  = fmaxf(_eh, 0.0f); }
        APPLY16(ST_H1)
#undef ST_H1

        // ---- matvec 2: acc = b2 + fw2^T h1(scratch)
#define INIT_B2(p) { u64 _b = b2p[p]; A##p = _b; C##p = _b; E##p = _b; }
        APPLY16(INIT_B2)
#undef INIT_B2
#pragma unroll 1
        for (int i = 0; i < W; i++) {
            float v0, v1;
            unpk(pAB[i * TPB], v0, v1);
            float v2 = pC[i * TPB];
            u64 d0 = dup2(v0), d1 = dup2(v1), d2 = dup2(v2);
            ROWFMA3(s_fw2 + i * 32, d0, d1, d2);
        }

        // ---- acc = pre2. Record sign masks only.
#define ST_M2(p) {                                                         \
        float _al, _ah, _cl, _ch, _el, _eh;                                \
        unpk(A##p, _al, _ah); unpk(C##p, _cl, _ch); unpk(E##p, _el, _eh);  \
        m2a |= (_al > 0.0f) ? (1u << (2 * p))     : 0u;                    \
        m2a |= (_ah > 0.0f) ? (1u << (2 * p + 1)) : 0u;                    \
        m2b |= (_cl > 0.0f) ? (1u << (2 * p))     : 0u;                    \
        m2b |= (_ch > 0.0f) ? (1u << (2 * p + 1)) : 0u;                    \
        m2c |= (_el > 0.0f) ? (1u << (2 * p))     : 0u;                    \
        m2c |= (_eh > 0.0f) ? (1u << (2 * p + 1)) : 0u; }
        APPLY16(ST_M2)
#undef ST_M2

        // ---- matvec 3 (backward): acc = bw2^T (m2-masked w3)
#define ZERO_AC(p) { A##p = 0ull; C##p = 0ull; E##p = 0ull; }
        APPLY16(ZERO_AC)
#pragma unroll 1
        for (int i = 0; i < W; i++) {
            float w3i = s_w3[i];
            float ga = ((m2a >> i) & 1u) ? w3i : 0.0f;
            float gb = ((m2b >> i) & 1u) ? w3i : 0.0f;
            float gc = ((m2c >> i) & 1u) ? w3i : 0.0f;
            u64 d0 = dup2(ga), d1 = dup2(gb), d2 = dup2(gc);
            ROWFMA3(s_bw2 + i * 32, d0, d1, d2);
        }

        // ---- acc = g1raw. g1 = m1-masked -> scratch.
#define ST_G1(p) {                                                         \
        float _al, _ah, _cl, _ch, _el, _eh;                                \
        unpk(A##p, _al, _ah); unpk(C##p, _cl, _ch); unpk(E##p, _el, _eh);  \
        pAB[(2 * p) * TPB]     = pack2((m1a & (1u << (2 * p)))     ? _al : 0.0f, \
                                       (m1b & (1u << (2 * p)))     ? _cl : 0.0f); \
        pAB[(2 * p + 1) * TPB] = pack2((m1a & (1u << (2 * p + 1))) ? _ah : 0.0f, \
                                       (m1b & (1u << (2 * p + 1))) ? _ch : 0.0f); \
        pC[(2 * p) * TPB]      = (m1c & (1u << (2 * p)))     ? _el : 0.0f; \
        pC[(2 * p + 1) * TPB]  = (m1c & (1u << (2 * p + 1))) ? _eh : 0.0f; }
        APPLY16(ST_G1)
#undef ST_G1

        // ---- matvec 4 (backward): acc = bw1^T g1(scratch)
        APPLY16(ZERO_AC)
#undef ZERO_AC
#pragma unroll 1
        for (int i = 0; i < W; i++) {
            float v0, v1;
            unpk(pAB[i * TPB], v0, v1);
            float v2 = pC[i * TPB];
            u64 d0 = dup2(v0), d1 = dup2(v1), d2 = dup2(v2);
            ROWFMA3(s_bw1 + i * 32, d0, d1, d2);
        }

        // ---- dy = sum_k (pre0_k>0 ? w0y_k : 0) * g0raw_k
        float dy0 = 0.0f, dy1 = 0.0f, dy2 = 0.0f;
#define DYM(p) {                                                           \
        float _al, _ah, _cl, _ch, _el, _eh;                                \
        unpk(A##p, _al, _ah); unpk(C##p, _cl, _ch); unpk(E##p, _el, _eh);  \
        float _wl = s_w0y[2 * p], _wh = s_w0y[2 * p + 1];                  \
        dy0 = fmaf((m0a & (1u << (2 * p)))     ? _wl : 0.0f, _al, dy0);    \
        dy0 = fmaf((m0a & (1u << (2 * p + 1))) ? _wh : 0.0f, _ah, dy0);    \
        dy1 = fmaf((m0b & (1u << (2 * p)))     ? _wl : 0.0f, _cl, dy1);    \
        dy1 = fmaf((m0b & (1u << (2 * p + 1))) ? _wh : 0.0f, _ch, dy1);    \
        dy2 = fmaf((m0c & (1u << (2 * p)))     ? _wl : 0.0f, _el, dy2);    \
        dy2 = fmaf((m0c & (1u << (2 * p + 1))) ? _wh : 0.0f, _eh, dy2); }
        APPLY16(DYM)
#undef DYM

        y0 = fmaf(-INNER_LR, dy0, y0);
        y1 = fmaf(-INNER_LR, dy1, y1);
        y2 = fmaf(-INNER_LR, dy2, y2);
    }

    gOUT[s0] = y0;
    if (s1 < n) gOUT[s1] = y1;
    if (s2 < n) gOUT[s2] = y2;
}

extern "C" void kernel_launch(void* const* d_in, const int* in_sizes, int n_in,
                              void* d_out, int out_size) {
    const float* x  = (const float*)d_in[0];
    const float* w0 = (const float*)d_in[1];
    const float* b0 = (const float*)d_in[2];
    const float* w1 = (const float*)d_in[3];
    const float* b1 = (const float*)d_in[4];
    const float* w2 = (const float*)d_in[5];
    const float* b2 = (const float*)d_in[6];
    const float* w3 = (const float*)d_in[7];
    const float* ymean = (const float*)d_in[9];  // d_in[8] = b3 (unused)
    float* out = (float*)d_out;

    int n = in_sizes[0];
    int blocks = (n + 3 * TPB - 1) / (3 * TPB);
    BaseEBM_kernel<<<blocks, TPB>>>(x, w0, b0, w1, b1, w2, b2, w3, ymean, out, n);
}

// round 11
// speedup vs baseline: 1.1475x; 1.1475x over previous
#include <cuda_runtime.h>

// BaseEBM: 1M samples x 20 GD steps on y through fixed 2->32->32->32->1
// ReLU MLP. R11 = R9's proven 2-sample/f32x2 structure with HIGHER WARP
// RESIDENCY: R9/R10 profiles showed the limiter is issue/latency exposure
// at 12 warps/SM (register-file cap at 166 regs). Fix: TPB=128 +
// __launch_bounds__(128,4) -> 128-reg cap -> 16 warps/SM. Smem rises to
// 49KB/CTA (scratch 32KB + weights 17KB) -> dynamic smem + opt-in attr.
// Real row loops (#pragma unroll 1) retained -- they are what keeps ptxas
// live ranges bounded (the R5/R7/R8 spill killer).

#define W 32
#define INNER_STEPS 20
#define INNER_LR 0.1f
#define TPB 128

using u64 = unsigned long long;

// dynamic smem layout (bytes):
//   [0      : 16384)  s_fw1|s_fw2|s_bw2|s_bw1  (4 x 1024 floats)
//   [16384  : 17152)  s_w0x|s_w0y|s_b0|s_b1|s_b2|s_w3 (6 x 32 floats)
//   [17152  : 49920)  scr: u64[32 * TPB]
#define SMEM_FW1   0
#define SMEM_FW2   (1024 * 4)
#define SMEM_BW2   (2048 * 4)
#define SMEM_BW1   (3072 * 4)
#define SMEM_SML   (4096 * 4)
#define SMEM_SCR   17152
#define SMEM_TOTAL (SMEM_SCR + W * TPB * 8)

__device__ __forceinline__ u64 fma2(u64 a, u64 b, u64 c) {
    u64 d;
    asm("fma.rn.f32x2 %0, %1, %2, %3;" : "=l"(d) : "l"(a), "l"(b), "l"(c));
    return d;
}
__device__ __forceinline__ u64 dup2(float x) {
    u64 d;
    asm("mov.b64 %0, {%1, %1};" : "=l"(d) : "f"(x));
    return d;
}
__device__ __forceinline__ u64 pack2(float lo, float hi) {
    u64 d;
    asm("mov.b64 %0, {%1, %2};" : "=l"(d) : "f"(lo), "f"(hi));
    return d;
}
__device__ __forceinline__ void unpk(u64 v, float& lo, float& hi) {
    asm("mov.b64 {%0, %1}, %2;" : "=f"(lo), "=f"(hi) : "l"(v));
}

#define APPLY16(M) M(0) M(1) M(2) M(3) M(4) M(5) M(6) M(7) \
                   M(8) M(9) M(10) M(11) M(12) M(13) M(14) M(15)

// A0..A15 += D0 * row[pair]; C0..C15 += D1 * row[pair]. 8x LDS.128, 32x FFMA2.
#define ROWFMA2(ROW, D0, D1) do {                                          \
    const ulonglong2* _r = reinterpret_cast<const ulonglong2*>(ROW);       \
    {                                                                      \
        ulonglong2 _wa = _r[0], _wb = _r[1], _wc = _r[2], _wd = _r[3];     \
        A0 = fma2(_wa.x, D0, A0); C0 = fma2(_wa.x, D1, C0);                \
        A1 = fma2(_wa.y, D0, A1); C1 = fma2(_wa.y, D1, C1);                \
        A2 = fma2(_wb.x, D0, A2); C2 = fma2(_wb.x, D1, C2);                \
        A3 = fma2(_wb.y, D0, A3); C3 = fma2(_wb.y, D1, C3);                \
        A4 = fma2(_wc.x, D0, A4); C4 = fma2(_wc.x, D1, C4);                \
        A5 = fma2(_wc.y, D0, A5); C5 = fma2(_wc.y, D1, C5);                \
        A6 = fma2(_wd.x, D0, A6); C6 = fma2(_wd.x, D1, C6);                \
        A7 = fma2(_wd.y, D0, A7); C7 = fma2(_wd.y, D1, C7);                \
    }                                                                      \
    {                                                                      \
        ulonglong2 _wa = _r[4], _wb = _r[5], _wc = _r[6], _wd = _r[7];     \
        A8  = fma2(_wa.x, D0, A8 ); C8  = fma2(_wa.x, D1, C8 );            \
        A9  = fma2(_wa.y, D0, A9 ); C9  = fma2(_wa.y, D1, C9 );            \
        A10 = fma2(_wb.x, D0, A10); C10 = fma2(_wb.x, D1, C10);            \
        A11 = fma2(_wb.y, D0, A11); C11 = fma2(_wb.y, D1, C11);            \
        A12 = fma2(_wc.x, D0, A12); C12 = fma2(_wc.x, D1, C12);            \
        A13 = fma2(_wc.y, D0, A13); C13 = fma2(_wc.y, D1, C13);            \
        A14 = fma2(_wd.x, D0, A14); C14 = fma2(_wd.x, D1, C14);            \
        A15 = fma2(_wd.y, D0, A15); C15 = fma2(_wd.y, D1, C15);            \
    }                                                                      \
} while (0)

__global__ __launch_bounds__(TPB, 4) void BaseEBM_kernel(
    const float* __restrict__ gX,
    const float* __restrict__ gW0,   // [32,2]
    const float* __restrict__ gB0,   // [32]
    const float* __restrict__ gW1,   // [32,32]
    const float* __restrict__ gB1,   // [32]
    const float* __restrict__ gW2,   // [32,32]
    const float* __restrict__ gB2,   // [32]
    const float* __restrict__ gW3,   // [32]
    const float* __restrict__ gYM,   // [1]
    float* __restrict__ gOUT,
    int n) {
    extern __shared__ char dsm[];
    float* s_fw1 = reinterpret_cast<float*>(dsm + SMEM_FW1);  // fw1[i*32+j]=W1[j][i]
    float* s_fw2 = reinterpret_cast<float*>(dsm + SMEM_FW2);  // fw2[i*32+j]=W2[j][i]
    float* s_bw2 = reinterpret_cast<float*>(dsm + SMEM_BW2);  // bw2[i*32+j]=W2[i][j]
    float* s_bw1 = reinterpret_cast<float*>(dsm + SMEM_BW1);  // bw1[i*32+j]=W1[i][j]
    float* s_w0x = reinterpret_cast<float*>(dsm + SMEM_SML);
    float* s_w0y = s_w0x + W;
    float* s_b0  = s_w0y + W;
    float* s_b1  = s_b0 + W;
    float* s_b2  = s_b1 + W;
    float* s_w3  = s_b2 + W;
    u64*   scr   = reinterpret_cast<u64*>(dsm + SMEM_SCR);

    const int tid = threadIdx.x;
#pragma unroll
    for (int k = 0; k < (W * W) / TPB; k++) {
        int e = k * TPB + tid;
        int i = e >> 5, j = e & 31;
        s_fw1[e] = gW1[j * W + i];
        s_fw2[e] = gW2[j * W + i];
        s_bw2[e] = gW2[e];
        s_bw1[e] = gW1[e];
    }
    if (tid < W) {
        s_w0x[tid] = gW0[2 * tid + 0];
        s_w0y[tid] = gW0[2 * tid + 1];
        s_b0[tid]  = gB0[tid];
        s_b1[tid]  = gB1[tid];
        s_b2[tid]  = gB2[tid];
        s_w3[tid]  = gW3[tid];
    }
    __syncthreads();

    const int s0 = blockIdx.x * (2 * TPB) + tid;
    const int s1 = s0 + TPB;
    if (s0 >= n) return;

    const float x0 = gX[s0];
    const float x1 = (s1 < n) ? gX[s1] : 0.0f;
    float y0 = gYM[0];
    float y1 = y0;

    const u64* b1p = reinterpret_cast<const u64*>(s_b1);
    const u64* b2p = reinterpret_cast<const u64*>(s_b2);
    u64* pS = scr + tid;

    u64 A0, A1, A2, A3, A4, A5, A6, A7;
    u64 A8, A9, A10, A11, A12, A13, A14, A15;
    u64 C0, C1, C2, C3, C4, C5, C6, C7;
    u64 C8, C9, C10, C11, C12, C13, C14, C15;

#pragma unroll 1
    for (int s = 0; s < INNER_STEPS; s++) {
        unsigned m0a = 0u, m0b = 0u, m1a = 0u, m1b = 0u, m2a = 0u, m2b = 0u;

        // ---- matvec 1: acc = b1 + fw1^T relu(pre0)
#define INIT_B1(p) { u64 _b = b1p[p]; A##p = _b; C##p = _b; }
        APPLY16(INIT_B1)
#undef INIT_B1
#pragma unroll 1
        for (int i = 0; i < W; i++) {
            float wx = s_w0x[i], wy = s_w0y[i], b = s_b0[i];
            float pa = fmaf(y0, wy, fmaf(x0, wx, b));
            float pb = fmaf(y1, wy, fmaf(x1, wx, b));
            m0a |= (pa > 0.0f) ? (1u << i) : 0u;
            m0b |= (pb > 0.0f) ? (1u << i) : 0u;
            u64 d0 = dup2(fmaxf(pa, 0.0f));
            u64 d1 = dup2(fmaxf(pb, 0.0f));
            ROWFMA2(s_fw1 + i * 32, d0, d1);
        }

        // ---- acc = pre1. h1 = relu -> scratch; m1 recorded.
#define ST_H1(p) {                                                         \
        float _al, _ah, _cl, _ch;                                          \
        unpk(A##p, _al, _ah); unpk(C##p, _cl, _ch);                        \
        m1a |= (_al > 0.0f) ? (1u << (2 * p))     : 0u;                    \
        m1a |= (_ah > 0.0f) ? (1u << (2 * p + 1)) : 0u;                    \
        m1b |= (_cl > 0.0f) ? (1u << (2 * p))     : 0u;                    \
        m1b |= (_ch > 0.0f) ? (1u << (2 * p + 1)) : 0u;                    \
        pS[(2 * p) * TPB]     = pack2(fmaxf(_al, 0.0f), fmaxf(_cl, 0.0f)); \
        pS[(2 * p + 1) * TPB] = pack2(fmaxf(_ah, 0.0f), fmaxf(_ch, 0.0f)); }
        APPLY16(ST_H1)
#undef ST_H1

        // ---- matvec 2: acc = b2 + fw2^T h1(scratch)
#define INIT_B2(p) { u64 _b = b2p[p]; A##p = _b; C##p = _b; }
        APPLY16(INIT_B2)
#undef INIT_B2
#pragma unroll 1
        for (int i = 0; i < W; i++) {
            float v0, v1;
            unpk(pS[i * TPB], v0, v1);
            u64 d0 = dup2(v0), d1 = dup2(v1);
            ROWFMA2(s_fw2 + i * 32, d0, d1);
        }

        // ---- acc = pre2. Record sign masks only (g2 = m2 ? w3 : 0).
#define ST_M2(p) {                                                         \
        float _al, _ah, _cl, _ch;                                          \
        unpk(A##p, _al, _ah); unpk(C##p, _cl, _ch);                        \
        m2a |= (_al > 0.0f) ? (1u << (2 * p))     : 0u;                    \
        m2a |= (_ah > 0.0f) ? (1u << (2 * p + 1)) : 0u;                    \
        m2b |= (_cl > 0.0f) ? (1u << (2 * p))     : 0u;                    \
        m2b |= (_ch > 0.0f) ? (1u << (2 * p + 1)) : 0u; }
        APPLY16(ST_M2)
#undef ST_M2

        // ---- matvec 3 (backward): acc = bw2^T (m2-masked w3)
#define ZERO_AC(p) { A##p = 0ull; C##p = 0ull; }
        APPLY16(ZERO_AC)
#pragma unroll 1
        for (int i = 0; i < W; i++) {
            float w3i = s_w3[i];
            float ga = ((m2a >> i) & 1u) ? w3i : 0.0f;
            float gb = ((m2b >> i) & 1u) ? w3i : 0.0f;
            u64 d0 = dup2(ga), d1 = dup2(gb);
            ROWFMA2(s_bw2 + i * 32, d0, d1);
        }

        // ---- acc = g1raw. g1 = m1-masked -> scratch.
#define ST_G1(p) {                                                         \
        float _al, _ah, _cl, _ch;                                          \
        unpk(A##p, _al, _ah); unpk(C##p, _cl, _ch);                        \
        pS[(2 * p) * TPB]     = pack2((m1a & (1u << (2 * p)))     ? _al : 0.0f, \
                                      (m1b & (1u << (2 * p)))     ? _cl : 0.0f); \
        pS[(2 * p + 1) * TPB] = pack2((m1a & (1u << (2 * p + 1))) ? _ah : 0.0f, \
                                      (m1b & (1u << (2 * p + 1))) ? _ch : 0.0f); }
        APPLY16(ST_G1)
#undef ST_G1

        // ---- matvec 4 (backward): acc = bw1^T g1(scratch)
        APPLY16(ZERO_AC)
#undef ZERO_AC
#pragma unroll 1
        for (int i = 0; i < W; i++) {
            float v0, v1;
            unpk(pS[i * TPB], v0, v1);
            u64 d0 = dup2(v0), d1 = dup2(v1);
            ROWFMA2(s_bw1 + i * 32, d0, d1);
        }

        // ---- dy = sum_k (pre0_k>0 ? w0y_k : 0) * g0raw_k
        float dy0 = 0.0f, dy1 = 0.0f;
#define DYM(p) {                                                           \
        float _al, _ah, _cl, _ch;                                          \
        unpk(A##p, _al, _ah); unpk(C##p, _cl, _ch);                        \
        float _wl = s_w0y[2 * p], _wh = s_w0y[2 * p + 1];                  \
        dy0 = fmaf((m0a & (1u << (2 * p)))     ? _wl : 0.0f, _al, dy0);    \
        dy0 = fmaf((m0a & (1u << (2 * p + 1))) ? _wh : 0.0f, _ah, dy0);    \
        dy1 = fmaf((m0b & (1u << (2 * p)))     ? _wl : 0.0f, _cl, dy1);    \
        dy1 = fmaf((m0b & (1u << (2 * p + 1))) ? _wh : 0.0f, _ch, dy1); }
        APPLY16(DYM)
#undef DYM

        y0 = fmaf(-INNER_LR, dy0, y0);
        y1 = fmaf(-INNER_LR, dy1, y1);
    }

    gOUT[s0] = y0;
    if (s1 < n) gOUT[s1] = y1;
}

extern "C" void kernel_launch(void* const* d_in, const int* in_sizes, int n_in,
                              void* d_out, int out_size) {
    const float* x  = (const float*)d_in[0];
    const float* w0 = (const float*)d_in[1];
    const float* b0 = (const float*)d_in[2];
    const float* w1 = (const float*)d_in[3];
    const float* b1 = (const float*)d_in[4];
    const float* w2 = (const float*)d_in[5];
    const float* b2 = (const float*)d_in[6];
    const float* w3 = (const float*)d_in[7];
    const float* ymean = (const float*)d_in[9];  // d_in[8] = b3 (unused)
    float* out = (float*)d_out;

    // Opt in to >48KB dynamic smem (host attribute set, not an allocation;
    // idempotent and executed immediately, so graph-capture safe).
    cudaFuncSetAttribute(BaseEBM_kernel,
                         cudaFuncAttributeMaxDynamicSharedMemorySize,
                         SMEM_TOTAL);

    int n = in_sizes[0];
    int blocks = (n + 2 * TPB - 1) / (2 * TPB);
    BaseEBM_kernel<<<blocks, TPB, SMEM_TOTAL>>>(x, w0, b0, w1, b1, w2, b2, w3,
                                                ymean, out, n);
}